// round 16
// baseline (speedup 1.0000x reference)
#include <cuda_runtime.h>
#include <cuda_fp16.h>
#include <math.h>
#include <stdint.h>

#define BSZ     2
#define SLEN    2048
#define HIDDEN  512
#define FFNDIM  2048
#define HEADS   8
#define KD      64
#define VDIM    1024
#define HSZ     128
#define ROWS    (BSZ*SLEN)          // 4096
#define SCALING 0.125f
#define LN_EPS  1e-5f
#define LOG2E   1.44269504f

#define WT_PER_LAYER 3670016
#define OFF_WQ 0
#define OFF_WK 262144
#define OFF_WV 524288
#define OFF_WO 1048576
#define OFF_W1 1572864
#define OFF_W2 2621440

typedef __half f16;

// ---------------- scratch ---------------------------------------------------
__device__ float g_proj[ROWS*HIDDEN];
__device__ float g_y[ROWS*HIDDEN];
__device__ float g_x[ROWS*HIDDEN];

__device__ f16 g_xh[ROWS*HIDDEN];
__device__ f16 g_qh[ROWS*HIDDEN];                            // rotary'd * log2e
__device__ f16 g_kh[ROWS*HIDDEN];                            // rotary'd
__device__ f16 g_vt[ROWS*VDIM];                              // [b][n][s]
__device__ f16 g_att[ROWS*VDIM];
__device__ f16 g_yh[ROWS*HIDDEN];
__device__ f16 g_f1h[ROWS*FFNDIM];
__device__ f16 g_wt[2*WT_PER_LAYER];
__device__ float2 g_rope[SLEN*32];

// ---------------- helpers ---------------------------------------------------
__device__ __forceinline__ unsigned h2pack(float lo, float hi) {
    unsigned r;
    asm("cvt.rn.f16x2.f32 %0, %1, %2;" : "=r"(r) : "f"(hi), "f"(lo));
    return r;
}

__device__ __forceinline__ void mma16816(float* c,
                                         unsigned a0, unsigned a1, unsigned a2, unsigned a3,
                                         unsigned b0, unsigned b1) {
    asm volatile(
        "mma.sync.aligned.m16n8k16.row.col.f32.f16.f16.f32 "
        "{%0,%1,%2,%3}, {%4,%5,%6,%7}, {%8,%9}, {%0,%1,%2,%3};\n"
        : "+f"(c[0]), "+f"(c[1]), "+f"(c[2]), "+f"(c[3])
        : "r"(a0), "r"(a1), "r"(a2), "r"(a3), "r"(b0), "r"(b1));
}

__device__ __forceinline__ void ldsm4(unsigned* r, unsigned a) {
    asm volatile("ldmatrix.sync.aligned.m8n8.x4.shared.b16 {%0,%1,%2,%3}, [%4];\n"
                 : "=r"(r[0]), "=r"(r[1]), "=r"(r[2]), "=r"(r[3]) : "r"(a));
}

__device__ __forceinline__ void cp16(unsigned dst, const void* src) {
    asm volatile("cp.async.cg.shared.global [%0], [%1], 16;\n" :: "r"(dst), "l"(src));
}

// ---------------- NT GEMM: C[M,N] = A[M,K] @ B[N,K]^T ----------------------
// BM = MT*32, BN = NT*32, BK=32, 256 threads, warps 2m x 4n,
// warp tile (MT*16) x (NT*8). A and B single fp16, 64B rows.
// OUT 0: fp32. 1: single f16. 4: fused QKV (rope q*log2e / rope k / transpose v).
template<int MT, int NT, bool BIAS, bool RELU, int OUT>
__global__ __launch_bounds__(256)
void gemm_f16(const f16* __restrict__ A, const f16* __restrict__ B,
              const float* __restrict__ bias, const float2* __restrict__ rope,
              float* __restrict__ Cf, f16* __restrict__ Ch,
              f16* __restrict__ Chk, f16* __restrict__ Chv,
              int K, int lda, int ldb, int ldc) {
    extern __shared__ char dsm[];
    unsigned s0 = (unsigned)__cvta_generic_to_shared(dsm);
    s0 = (s0 + 1023) & ~1023u;

    constexpr int BM     = MT * 32;
    constexpr int BN     = NT * 32;
    constexpr int ABYTES = BM * 64;
    constexpr int STAGE  = ABYTES + BN * 64;
    constexpr int ACH    = BM * 4;
    constexpr int NCH    = (ACH + BN * 4) / 256;

    const int bm = blockIdx.y * BM, bn = blockIdx.x * BN;
    const int tid = threadIdx.x, lane = tid & 31, warp = tid >> 5;
    const int wm = (warp >> 2) * (MT * 16), wn = (warp & 3) * (NT * 8);
    const int g = lane >> 2, tig = lane & 3;

    float acc[MT][NT][4] = {};

    auto issue = [&](int kt, unsigned SA) {
        const unsigned SB = SA + ABYTES;
#pragma unroll
        for (int i = 0; i < NCH; i++) {
            const int lin = i * 256 + tid;
            if (lin < ACH) {
                const int row = lin >> 2, c = lin & 3;
                cp16(SA + row * 64 + ((c ^ ((row >> 1) & 3)) << 4),
                     A + (size_t)(bm + row) * lda + kt + c * 8);
            } else {
                const int idx = lin - ACH;
                const int row = idx >> 2, c = idx & 3;
                cp16(SB + row * 64 + ((c ^ ((row >> 1) & 3)) << 4),
                     B + (size_t)(bn + row) * ldb + kt + c * 8);
            }
        }
        asm volatile("cp.async.commit_group;\n");
    };

    const int nk = K >> 5;
    issue(0, s0);

    for (int t = 0; t < nk; t++) {
        const unsigned SA = s0 + (t & 1) * STAGE;
        const unsigned SB = SA + ABYTES;
        if (t + 1 < nk) {
            issue((t + 1) * 32, s0 + ((t + 1) & 1) * STAGE);
            asm volatile("cp.async.wait_group 1;\n");
        } else {
            asm volatile("cp.async.wait_group 0;\n");
        }
        __syncthreads();

#pragma unroll
        for (int ks = 0; ks < 2; ks++) {
            unsigned ah[MT][4], bh[NT][2];
#pragma unroll
            for (int mt = 0; mt < MT; mt++) {
                const int r  = wm + mt * 16 + (lane & 15);
                const int lc = 2 * ks + (lane >> 4);
                ldsm4(ah[mt], SA + r * 64 + ((lc ^ ((r >> 1) & 3)) << 4));
            }
#pragma unroll
            for (int p = 0; p < NT / 2; p++) {
                const int r  = wn + p * 16 + (lane & 7) + ((lane >> 4) << 3);
                const int lc = 2 * ks + ((lane >> 3) & 1);
                unsigned th[4];
                ldsm4(th, SB + r * 64 + ((lc ^ ((r >> 1) & 3)) << 4));
                bh[2*p][0]   = th[0]; bh[2*p][1]   = th[1];
                bh[2*p+1][0] = th[2]; bh[2*p+1][1] = th[3];
            }
#pragma unroll
            for (int mt = 0; mt < MT; mt++)
#pragma unroll
                for (int nt = 0; nt < NT; nt++)
                    mma16816(acc[mt][nt], ah[mt][0], ah[mt][1], ah[mt][2], ah[mt][3],
                             bh[nt][0], bh[nt][1]);
        }
        __syncthreads();
    }

    // ---------------- epilogue ----------------
#pragma unroll
    for (int mt = 0; mt < MT; mt++) {
#pragma unroll
        for (int nt = 0; nt < NT; nt++) {
            const int row = bm + wm + mt * 16 + g;
            const int col = bn + wn + nt * 8 + tig * 2;
            float c0 = acc[mt][nt][0], c1 = acc[mt][nt][1];
            float c2 = acc[mt][nt][2], c3 = acc[mt][nt][3];
            if (BIAS) {
                const float b0 = bias[col], b1 = bias[col + 1];
                c0 += b0; c1 += b1; c2 += b0; c3 += b1;
            }
            if (RELU) {
                c0 = fmaxf(c0, 0.f); c1 = fmaxf(c1, 0.f);
                c2 = fmaxf(c2, 0.f); c3 = fmaxf(c3, 0.f);
            }
            if (OUT == 0) {
                *(float2*)&Cf[(size_t)row * ldc + col]       = make_float2(c0, c1);
                *(float2*)&Cf[(size_t)(row + 8) * ldc + col] = make_float2(c2, c3);
            } else if (OUT == 1) {
                *(__half2*)&Ch[(size_t)row * ldc + col] =
                    __halves2half2(__float2half_rn(c0), __float2half_rn(c1));
                *(__half2*)&Ch[(size_t)(row + 8) * ldc + col] =
                    __halves2half2(__float2half_rn(c2), __float2half_rn(c3));
            } else {
                // fused QKV: [0,512)=Q rope*log2e, [512,1024)=K rope, [1024,2048)=V^T
                if (col < 1024) {
                    const int d2 = (col & 63) >> 1;
                    const float2 r0 = rope[(size_t)(row & 2047) * 32 + d2];
                    const float2 r1 = rope[(size_t)((row + 8) & 2047) * 32 + d2];
                    const bool isq = (col < 512);
                    const float sc = isq ? LOG2E : 1.f;
                    f16* dst = isq ? Ch : Chk;
                    const int cc = col & 511;
                    *(__half2*)&dst[(size_t)row * HIDDEN + cc] =
                        __halves2half2(__float2half_rn(sc * (c0 * r0.x - c1 * r0.y)),
                                       __float2half_rn(sc * (c1 * r0.x + c0 * r0.y)));
                    *(__half2*)&dst[(size_t)(row + 8) * HIDDEN + cc] =
                        __halves2half2(__float2half_rn(sc * (c2 * r1.x - c3 * r1.y)),
                                       __float2half_rn(sc * (c3 * r1.x + c2 * r1.y)));
                } else {
                    const int n = col - 1024;
                    const size_t basev = (size_t)(row >> 11) * VDIM * SLEN;
                    const int s1 = row & 2047, s2 = (row + 8) & 2047;
                    Chv[basev + (size_t)n       * SLEN + s1] = __float2half_rn(c0);
                    Chv[basev + (size_t)(n + 1) * SLEN + s1] = __float2half_rn(c1);
                    Chv[basev + (size_t)n       * SLEN + s2] = __float2half_rn(c2);
                    Chv[basev + (size_t)(n + 1) * SLEN + s2] = __float2half_rn(c3);
                }
            }
        }
    }
}

// ---------------- flash attention: Q in regs (log2-domain), 3-stage KV ------
__global__ __launch_bounds__(256, 1)
void flash_attn(const f16* __restrict__ Q, const f16* __restrict__ Kp,
                const f16* __restrict__ V, f16* __restrict__ Oh) {
    extern __shared__ char dsm[];
    unsigned s0 = (unsigned)__cvta_generic_to_shared(dsm);
    s0 = (s0 + 1023) & ~1023u;
    const int qt = blockIdx.x, z = blockIdx.y;
    const int b = z >> 3, h = z & 7;
    const int tid = threadIdx.x, lane = tid & 31, warp = tid >> 5;

    const f16* Qb = Q + ((size_t)(b * SLEN + qt * 128)) * HIDDEN + h * KD;
    const f16* Kb = Kp + (size_t)b * SLEN * HIDDEN + h * KD;
    const f16* Vb = V + ((size_t)b * VDIM + h * HSZ) * SLEN;

    const int rA = warp * 16 + (lane & 15);
    const int rB = (lane & 7) + ((lane >> 4) << 3);
    const int cBsel = (lane >> 3) & 1;

    // stage Q via smem into persistent regs
#pragma unroll
    for (int i = 0; i < 4; i++) {
        const int lin = i * 256 + tid;
        const int row = lin >> 3, c = lin & 7;
        cp16(s0 + row * 128 + ((c ^ (row & 7)) << 4), Qb + (size_t)row * HIDDEN + c * 8);
    }
    asm volatile("cp.async.commit_group;\ncp.async.wait_group 0;\n");
    __syncthreads();
    unsigned aq[4][4];
#pragma unroll
    for (int ks = 0; ks < 4; ks++) {
        const int lc = ks * 2 + (lane >> 4);
        ldsm4(aq[ks], s0 + rA * 128 + ((lc ^ (rA & 7)) << 4));
    }
    __syncthreads();

    auto issue_kv = [&](int kt) {
        const unsigned SK = s0 + (kt % 3) * 49152;
        const unsigned SV = SK + 16384;
#pragma unroll
        for (int i = 0; i < 12; i++) {
            const int lin = i * 256 + tid;
            if (lin < 1024) {
                const int row = lin >> 3, c = lin & 7;
                cp16(SK + row * 128 + ((c ^ (row & 7)) << 4),
                     Kb + (size_t)(kt * 128 + row) * HIDDEN + c * 8);
            } else {
                const int idx = lin - 1024;
                const int n = idx >> 4, c = idx & 15;
                cp16(SV + n * 256 + ((c ^ (n & 7)) << 4),
                     Vb + (size_t)n * SLEN + kt * 128 + c * 8);
            }
        }
        asm volatile("cp.async.commit_group;\n");
    };
    issue_kv(0);
    issue_kv(1);

    float O[16][4] = {};
    float m0 = -INFINITY, m1 = -INFINITY, l0 = 0.f, l1 = 0.f;

    for (int t = 0; t < 16; t++) {
        const unsigned SK = s0 + (t % 3) * 49152;
        const unsigned SV = SK + 16384;
        if (t + 2 < 16) {
            issue_kv(t + 2);
            asm volatile("cp.async.wait_group 2;\n");
        } else if (t + 1 < 16) {
            asm volatile("cp.async.wait_group 1;\n");
        } else {
            asm volatile("cp.async.wait_group 0;\n");
        }
        __syncthreads();

        // S = Q K^T  (already in log2 domain: Q pre-scaled by log2e)
        float S[16][4] = {};
#pragma unroll
        for (int ks = 0; ks < 4; ks++) {
            const int lcB = ks * 2 + cBsel;
#pragma unroll
            for (int p = 0; p < 8; p++) {
                const int r2 = p * 16 + rB;
                unsigned tb[4];
                ldsm4(tb, SK + r2 * 128 + ((lcB ^ (r2 & 7)) << 4));
                mma16816(S[2*p],   aq[ks][0], aq[ks][1], aq[ks][2], aq[ks][3], tb[0], tb[1]);
                mma16816(S[2*p+1], aq[ks][0], aq[ks][1], aq[ks][2], aq[ks][3], tb[2], tb[3]);
            }
        }

        // online softmax in base-2
        float mx0 = -INFINITY, mx1 = -INFINITY;
#pragma unroll
        for (int nt = 0; nt < 16; nt++) {
            mx0 = fmaxf(mx0, fmaxf(S[nt][0], S[nt][1]));
            mx1 = fmaxf(mx1, fmaxf(S[nt][2], S[nt][3]));
        }
        mx0 = fmaxf(mx0, __shfl_xor_sync(0xffffffffu, mx0, 1));
        mx0 = fmaxf(mx0, __shfl_xor_sync(0xffffffffu, mx0, 2));
        mx1 = fmaxf(mx1, __shfl_xor_sync(0xffffffffu, mx1, 1));
        mx1 = fmaxf(mx1, __shfl_xor_sync(0xffffffffu, mx1, 2));
        const float nm0 = fmaxf(m0, mx0), nm1 = fmaxf(m1, mx1);
        const float sc0 = exp2f(m0 - nm0), sc1 = exp2f(m1 - nm1);
        m0 = nm0; m1 = nm1;
        float rs0 = 0.f, rs1 = 0.f;
#pragma unroll
        for (int nt = 0; nt < 16; nt++) {
            S[nt][0] = exp2f(S[nt][0] - nm0);
            S[nt][1] = exp2f(S[nt][1] - nm0);
            S[nt][2] = exp2f(S[nt][2] - nm1);
            S[nt][3] = exp2f(S[nt][3] - nm1);
            rs0 += S[nt][0] + S[nt][1];
            rs1 += S[nt][2] + S[nt][3];
            O[nt][0] *= sc0; O[nt][1] *= sc0;
            O[nt][2] *= sc1; O[nt][3] *= sc1;
        }
        rs0 += __shfl_xor_sync(0xffffffffu, rs0, 1);
        rs0 += __shfl_xor_sync(0xffffffffu, rs0, 2);
        rs1 += __shfl_xor_sync(0xffffffffu, rs1, 1);
        rs1 += __shfl_xor_sync(0xffffffffu, rs1, 2);
        l0 = l0 * sc0 + rs0;
        l1 = l1 * sc1 + rs1;

        // O += P V
#pragma unroll
        for (int j = 0; j < 8; j++) {
            const unsigned a0 = h2pack(S[2*j][0],   S[2*j][1]);
            const unsigned a1 = h2pack(S[2*j][2],   S[2*j][3]);
            const unsigned a2 = h2pack(S[2*j+1][0], S[2*j+1][1]);
            const unsigned a3 = h2pack(S[2*j+1][2], S[2*j+1][3]);
            const int lcV = j * 2 + cBsel;
#pragma unroll
            for (int p = 0; p < 8; p++) {
                const int r2 = p * 16 + rB;
                unsigned tb[4];
                ldsm4(tb, SV + r2 * 256 + ((lcV ^ (r2 & 7)) << 4));
                mma16816(O[2*p],   a0, a1, a2, a3, tb[0], tb[1]);
                mma16816(O[2*p+1], a0, a1, a2, a3, tb[2], tb[3]);
            }
        }
        __syncthreads();
    }

    const float inv0 = SCALING / l0, inv1 = SCALING / l1;
    const int g = lane >> 2, tg = lane & 3;
    const int srow = qt * 128 + warp * 16 + g;
    const size_t base0 = ((size_t)(b * SLEN) + srow) * VDIM + h * HSZ;
    const size_t base1 = base0 + (size_t)8 * VDIM;
#pragma unroll
    for (int nt = 0; nt < 16; nt++) {
        const int col = nt * 8 + tg * 2;
        *(__half2*)&Oh[base0 + col] =
            __halves2half2(__float2half_rn(O[nt][0] * inv0), __float2half_rn(O[nt][1] * inv0));
        *(__half2*)&Oh[base1 + col] =
            __halves2half2(__float2half_rn(O[nt][2] * inv1), __float2half_rn(O[nt][3] * inv1));
    }
}

// ---------------- batched weight transpose + fp16 ---------------------------
struct TSegs {
    const float* src[12];
    int dstoff[12];
    int K[12], N[12], tile0[12];
};

__global__ __launch_bounds__(256)
void transpose_cvt_all(TSegs segs, f16* __restrict__ dstbase) {
    __shared__ float t[32][33];
    const int tb = blockIdx.x;
    int s = 0;
#pragma unroll
    for (int i = 1; i < 12; i++) if (tb >= segs.tile0[i]) s = i;
    const int local = tb - segs.tile0[s];
    const int tilesX = segs.N[s] >> 5;
    const int nb = (local % tilesX) << 5;
    const int kb = (local / tilesX) << 5;
    const float* src = segs.src[s];
    f16* dst = dstbase + segs.dstoff[s];
    const int K = segs.K[s], N = segs.N[s];
    const int tx = threadIdx.x & 31, ty = threadIdx.x >> 5;
#pragma unroll
    for (int i = ty; i < 32; i += 8)
        t[i][tx] = src[(size_t)(kb + i) * N + nb + tx];
    __syncthreads();
#pragma unroll
    for (int i = ty; i < 32; i += 8)
        dst[(size_t)(nb + i) * K + kb + tx] = __float2half_rn(t[tx][i]);
}

// ---------------- rope table -------------------------------------------------
__global__ __launch_bounds__(256)
void build_rope(float2* __restrict__ rope) {
    const int idx = blockIdx.x * 256 + threadIdx.x;
    const int d2 = idx & 31, s = idx >> 5;
    const float base  = (2.f * d2 + 25.6f) / 89.6f;
    const float scale = powf(base, (float)(s - 1024) * (1.f / 512.f));
    const float invf  = powf(10000.f, -(float)d2 * (1.f / 32.f));
    float sv, cv;
    sincosf((float)s * invf, &sv, &cv);
    rope[idx] = make_float2(cv * scale, sv * scale);
}

// ---------------- elementwise fp32 -> fp16 ----------------------------------
__global__ __launch_bounds__(256)
void cvt_f16(const float* __restrict__ src, f16* __restrict__ dh) {
    const int i = blockIdx.x * 256 + threadIdx.x;
    dh[i] = __float2half_rn(src[i]);
}

// ---------------- block reduce / add_ln ------------------------------------
__device__ __forceinline__ float block_reduce(float v, float* sh, int op) {
#pragma unroll
    for (int o = 16; o; o >>= 1) {
        float t = __shfl_xor_sync(0xffffffffu, v, o);
        v = op ? fmaxf(v, t) : v + t;
    }
    if ((threadIdx.x & 31) == 0) sh[threadIdx.x >> 5] = v;
    __syncthreads();
    if (threadIdx.x < 32) {
        const int nw = blockDim.x >> 5;
        float t = (threadIdx.x < nw) ? sh[threadIdx.x] : (op ? -INFINITY : 0.f);
#pragma unroll
        for (int o = 16; o; o >>= 1) {
            float u = __shfl_xor_sync(0xffffffffu, t, o);
            t = op ? fmaxf(t, u) : t + u;
        }
        if (threadIdx.x == 0) sh[0] = t;
    }
    __syncthreads();
    float r = sh[0];
    __syncthreads();
    return r;
}

__global__ __launch_bounds__(256)
void add_ln(const float* __restrict__ a, const float* __restrict__ b,
            const float* __restrict__ g, const float* __restrict__ be,
            float* __restrict__ out, f16* __restrict__ oh) {
    __shared__ float sh[32];
    const size_t r = (size_t)blockIdx.x * HIDDEN;
    const int t = threadIdx.x;
    float v0 = a[r + t]       + b[r + t];
    float v1 = a[r + t + 256] + b[r + t + 256];
    float mean = block_reduce(v0 + v1, sh, 0) * (1.f / HIDDEN);
    float d0 = v0 - mean, d1 = v1 - mean;
    float var = block_reduce(d0 * d0 + d1 * d1, sh, 0) * (1.f / HIDDEN);
    float inv = rsqrtf(var + LN_EPS);
    const float o0 = d0 * inv * g[t]       + be[t];
    const float o1 = d1 * inv * g[t + 256] + be[t + 256];
    out[r + t]       = o0;
    out[r + t + 256] = o1;
    oh[r + t]       = __float2half_rn(o0);
    oh[r + t + 256] = __float2half_rn(o1);
}

// ---------------- driver ----------------------------------------------------
#define SMEM_WIDE  (2*24576 + 1024)   // MT4 NT8: stage 24K
#define SMEM_N512  (2*12288 + 1024)   // MT2 NT4: stage 12K
#define SMEM_FLASH (3*49152 + 1024)

extern "C" void kernel_launch(void* const* d_in, const int* in_sizes, int n_in,
                              void* d_out, int out_size) {
    const float* x   = (const float*)d_in[0];
    const float* Wq  = (const float*)d_in[1];
    const float* Wk  = (const float*)d_in[2];
    const float* Wv  = (const float*)d_in[3];
    const float* Wo  = (const float*)d_in[4];
    const float* W1  = (const float*)d_in[5];
    const float* b1  = (const float*)d_in[6];
    const float* W2  = (const float*)d_in[7];
    const float* b2  = (const float*)d_in[8];
    const float* g1  = (const float*)d_in[9];
    const float* be1 = (const float*)d_in[10];
    const float* g2  = (const float*)d_in[11];
    const float* be2 = (const float*)d_in[12];

    float *proj, *y, *xb;
    f16 *xh, *qh, *kh, *vt, *att, *yh, *f1h, *wt;
    float2* rope;
    cudaGetSymbolAddress((void**)&proj, g_proj);
    cudaGetSymbolAddress((void**)&y,    g_y);
    cudaGetSymbolAddress((void**)&xb,   g_x);
    cudaGetSymbolAddress((void**)&xh,   g_xh);
    cudaGetSymbolAddress((void**)&qh,   g_qh);
    cudaGetSymbolAddress((void**)&kh,   g_kh);
    cudaGetSymbolAddress((void**)&vt,   g_vt);
    cudaGetSymbolAddress((void**)&att,  g_att);
    cudaGetSymbolAddress((void**)&yh,   g_yh);
    cudaGetSymbolAddress((void**)&f1h,  g_f1h);
    cudaGetSymbolAddress((void**)&wt,   g_wt);
    cudaGetSymbolAddress((void**)&rope, g_rope);

    static bool attr_done = false;
    if (!attr_done) {
        cudaFuncSetAttribute((const void*)gemm_f16<4,8,false,false,4>, cudaFuncAttributeMaxDynamicSharedMemorySize, SMEM_WIDE);
        cudaFuncSetAttribute((const void*)gemm_f16<4,8,true,true,1>,   cudaFuncAttributeMaxDynamicSharedMemorySize, SMEM_WIDE);
        cudaFuncSetAttribute((const void*)gemm_f16<2,4,false,false,0>, cudaFuncAttributeMaxDynamicSharedMemorySize, SMEM_N512);
        cudaFuncSetAttribute((const void*)gemm_f16<2,4,true,false,0>,  cudaFuncAttributeMaxDynamicSharedMemorySize, SMEM_N512);
        cudaFuncSetAttribute((const void*)flash_attn,                  cudaFuncAttributeMaxDynamicSharedMemorySize, SMEM_FLASH);
        attr_done = true;
    }

    const dim3 T(256);

    // ---- one batched transpose launch for all 12 weight matrices ----
    {
        TSegs segs;
        int tile = 0;
        int si = 0;
        for (int l = 0; l < 2; l++) {
            const float* srcs[6] = {Wq + (size_t)l*HIDDEN*HIDDEN, Wk + (size_t)l*HIDDEN*HIDDEN,
                                    Wv + (size_t)l*HIDDEN*VDIM,   Wo + (size_t)l*VDIM*HIDDEN,
                                    W1 + (size_t)l*HIDDEN*FFNDIM, W2 + (size_t)l*FFNDIM*HIDDEN};
            const int offs[6] = {OFF_WQ, OFF_WK, OFF_WV, OFF_WO, OFF_W1, OFF_W2};
            const int Ks[6]   = {HIDDEN, HIDDEN, HIDDEN, VDIM, HIDDEN, FFNDIM};
            const int Ns[6]   = {HIDDEN, HIDDEN, VDIM, HIDDEN, FFNDIM, HIDDEN};
            for (int j = 0; j < 6; j++, si++) {
                segs.src[si] = srcs[j];
                segs.dstoff[si] = l * WT_PER_LAYER + offs[j];
                segs.K[si] = Ks[j]; segs.N[si] = Ns[j];
                segs.tile0[si] = tile;
                tile += (Ks[j] >> 5) * (Ns[j] >> 5);
            }
        }
        transpose_cvt_all<<<tile, T>>>(segs, wt);
    }

    build_rope<<<(SLEN*32)/256, T>>>(rope);
    cvt_f16<<<(ROWS*HIDDEN)/256, T>>>(x, xh);

    for (int i = 0; i < 2; i++) {
        const float* xin  = i ? xb : x;
        float*       xout = i ? (float*)d_out : xb;
        f16* base = wt + (size_t)i * WT_PER_LAYER;

        // fused QKV projection: N=2048 = [Q|K|V], tile 128x256
        gemm_f16<4,8,false,false,4><<<dim3(8, ROWS/128), T, SMEM_WIDE>>>(
            xh, base+OFF_WQ, nullptr, rope, nullptr, qh, kh, vt,
            HIDDEN, HIDDEN, HIDDEN, 0);

        flash_attn<<<dim3(SLEN/128, BSZ*HEADS), T, SMEM_FLASH>>>(qh, kh, vt, att);

        // output projection (tile 64x128)
        gemm_f16<2,4,false,false,0><<<dim3(4, ROWS/64), T, SMEM_N512>>>(
            att, base+OFF_WO, nullptr, nullptr, proj, nullptr, nullptr, nullptr,
            VDIM, VDIM, VDIM, HIDDEN);

        add_ln<<<ROWS, T>>>(xin, proj, g1 + i*HIDDEN, be1 + i*HIDDEN, y, yh);

        // FFN1 (tile 128x256) / FFN2 (tile 64x128)
        gemm_f16<4,8,true,true,1><<<dim3(8, ROWS/128), T, SMEM_WIDE>>>(
            yh, base+OFF_W1, b1 + i*FFNDIM, nullptr, nullptr, f1h, nullptr, nullptr,
            HIDDEN, HIDDEN, HIDDEN, FFNDIM);
        gemm_f16<2,4,true,false,0><<<dim3(4, ROWS/64), T, SMEM_N512>>>(
            f1h, base+OFF_W2, b2 + i*HIDDEN, nullptr, proj, nullptr, nullptr, nullptr,
            FFNDIM, FFNDIM, FFNDIM, HIDDEN);

        add_ln<<<ROWS, T>>>(y, proj, g2 + i*HIDDEN, be2 + i*HIDDEN, xout, xh);
    }
}

// round 17
// speedup vs baseline: 1.0548x; 1.0548x over previous
#include <cuda_runtime.h>
#include <cuda_fp16.h>
#include <math.h>
#include <stdint.h>

#define BSZ     2
#define SLEN    2048
#define HIDDEN  512
#define FFNDIM  2048
#define HEADS   8
#define KD      64
#define VDIM    1024
#define HSZ     128
#define ROWS    (BSZ*SLEN)          // 4096
#define SCALING 0.125f
#define LN_EPS  1e-5f
#define LOG2E   1.44269504f

#define WT_PER_LAYER 3670016
#define OFF_WQ 0
#define OFF_WK 262144
#define OFF_WV 524288
#define OFF_WO 1048576
#define OFF_W1 1572864
#define OFF_W2 2621440

typedef __half f16;

// ---------------- scratch ---------------------------------------------------
__device__ float g_proj[ROWS*HIDDEN];
__device__ float g_y[ROWS*HIDDEN];
__device__ float g_x[ROWS*HIDDEN];

__device__ f16 g_xh[ROWS*HIDDEN];
__device__ f16 g_qh[ROWS*HIDDEN];                            // rotary'd * log2e
__device__ f16 g_kh[ROWS*HIDDEN];                            // rotary'd
__device__ f16 g_vt[ROWS*VDIM];                              // [b][n][s]
__device__ f16 g_att[ROWS*VDIM];
__device__ f16 g_yh[ROWS*HIDDEN];
__device__ f16 g_f1h[ROWS*FFNDIM];
__device__ f16 g_wt[2*WT_PER_LAYER];
__device__ float2 g_rope[SLEN*32];

// ---------------- helpers ---------------------------------------------------
__device__ __forceinline__ unsigned h2pack(float lo, float hi) {
    unsigned r;
    asm("cvt.rn.f16x2.f32 %0, %1, %2;" : "=r"(r) : "f"(hi), "f"(lo));
    return r;
}

__device__ __forceinline__ void mma16816(float* c,
                                         unsigned a0, unsigned a1, unsigned a2, unsigned a3,
                                         unsigned b0, unsigned b1) {
    asm volatile(
        "mma.sync.aligned.m16n8k16.row.col.f32.f16.f16.f32 "
        "{%0,%1,%2,%3}, {%4,%5,%6,%7}, {%8,%9}, {%0,%1,%2,%3};\n"
        : "+f"(c[0]), "+f"(c[1]), "+f"(c[2]), "+f"(c[3])
        : "r"(a0), "r"(a1), "r"(a2), "r"(a3), "r"(b0), "r"(b1));
}

__device__ __forceinline__ void ldsm4(unsigned* r, unsigned a) {
    asm volatile("ldmatrix.sync.aligned.m8n8.x4.shared.b16 {%0,%1,%2,%3}, [%4];\n"
                 : "=r"(r[0]), "=r"(r[1]), "=r"(r[2]), "=r"(r[3]) : "r"(a));
}

__device__ __forceinline__ void cp16(unsigned dst, const void* src) {
    asm volatile("cp.async.cg.shared.global [%0], [%1], 16;\n" :: "r"(dst), "l"(src));
}

// ---------------- NT GEMM: C[M,N] = A[M,K] @ B[N,K]^T ----------------------
// BM = MT*32, BN=128, BK=32, 256 threads, warps 2m x 4n, warp tile (MT*16) x 32.
// 3-stage cp.async ring, ONE __syncthreads per k-tile.
// OUT 0: fp32. 1: single f16. 4: fused QKV (rope q*log2e / rope k / transpose v).
template<int MT, bool BIAS, bool RELU, int OUT>
__global__ __launch_bounds__(256)
void gemm_f16(const f16* __restrict__ A, const f16* __restrict__ B,
              const float* __restrict__ bias, const float2* __restrict__ rope,
              float* __restrict__ Cf, f16* __restrict__ Ch,
              f16* __restrict__ Chk, f16* __restrict__ Chv,
              int K, int lda, int ldb, int ldc) {
    extern __shared__ char dsm[];
    unsigned s0 = (unsigned)__cvta_generic_to_shared(dsm);
    s0 = (s0 + 1023) & ~1023u;

    constexpr int BM     = MT * 32;
    constexpr int ABYTES = BM * 64;
    constexpr int STAGE  = ABYTES + 8192;
    constexpr int ACH    = BM * 4;
    constexpr int NCH    = (ACH + 512) / 256;

    const int bm = blockIdx.y * BM, bn = blockIdx.x * 128;
    const int tid = threadIdx.x, lane = tid & 31, warp = tid >> 5;
    const int wm = (warp >> 2) * (MT * 16), wn = (warp & 3) * 32;
    const int g = lane >> 2, tig = lane & 3;

    float acc[MT][4][4] = {};

    auto issue = [&](int kt, unsigned SA) {
        const unsigned SB = SA + ABYTES;
#pragma unroll
        for (int i = 0; i < NCH; i++) {
            const int lin = i * 256 + tid;
            if (lin < ACH) {
                const int row = lin >> 2, c = lin & 3;
                cp16(SA + row * 64 + ((c ^ ((row >> 1) & 3)) << 4),
                     A + (size_t)(bm + row) * lda + kt + c * 8);
            } else {
                const int idx = lin - ACH;
                const int row = idx >> 2, c = idx & 3;
                cp16(SB + row * 64 + ((c ^ ((row >> 1) & 3)) << 4),
                     B + (size_t)(bn + row) * ldb + kt + c * 8);
            }
        }
        asm volatile("cp.async.commit_group;\n");
    };

    const int nk = K >> 5;
    issue(0, s0);
    if (nk > 1) issue(32, s0 + STAGE);

    for (int t = 0; t < nk; t++) {
        const unsigned SA = s0 + (t % 3) * STAGE;
        const unsigned SB = SA + ABYTES;
        if (t + 1 < nk) {
            asm volatile("cp.async.wait_group 1;\n");
        } else {
            asm volatile("cp.async.wait_group 0;\n");
        }
        __syncthreads();
        if (t + 2 < nk) issue((t + 2) * 32, s0 + ((t + 2) % 3) * STAGE);

#pragma unroll
        for (int ks = 0; ks < 2; ks++) {
            unsigned ah[MT][4], bh[4][2];
#pragma unroll
            for (int mt = 0; mt < MT; mt++) {
                const int r  = wm + mt * 16 + (lane & 15);
                const int lc = 2 * ks + (lane >> 4);
                ldsm4(ah[mt], SA + r * 64 + ((lc ^ ((r >> 1) & 3)) << 4));
            }
#pragma unroll
            for (int p = 0; p < 2; p++) {
                const int r  = wn + p * 16 + (lane & 7) + ((lane >> 4) << 3);
                const int lc = 2 * ks + ((lane >> 3) & 1);
                unsigned th[4];
                ldsm4(th, SB + r * 64 + ((lc ^ ((r >> 1) & 3)) << 4));
                bh[2*p][0]   = th[0]; bh[2*p][1]   = th[1];
                bh[2*p+1][0] = th[2]; bh[2*p+1][1] = th[3];
            }
#pragma unroll
            for (int mt = 0; mt < MT; mt++)
#pragma unroll
                for (int nt = 0; nt < 4; nt++)
                    mma16816(acc[mt][nt], ah[mt][0], ah[mt][1], ah[mt][2], ah[mt][3],
                             bh[nt][0], bh[nt][1]);
        }
    }

    // ---------------- epilogue ----------------
#pragma unroll
    for (int mt = 0; mt < MT; mt++) {
#pragma unroll
        for (int nt = 0; nt < 4; nt++) {
            const int row = bm + wm + mt * 16 + g;
            const int col = bn + wn + nt * 8 + tig * 2;
            float c0 = acc[mt][nt][0], c1 = acc[mt][nt][1];
            float c2 = acc[mt][nt][2], c3 = acc[mt][nt][3];
            if (BIAS) {
                const float b0 = bias[col], b1 = bias[col + 1];
                c0 += b0; c1 += b1; c2 += b0; c3 += b1;
            }
            if (RELU) {
                c0 = fmaxf(c0, 0.f); c1 = fmaxf(c1, 0.f);
                c2 = fmaxf(c2, 0.f); c3 = fmaxf(c3, 0.f);
            }
            if (OUT == 0) {
                *(float2*)&Cf[(size_t)row * ldc + col]       = make_float2(c0, c1);
                *(float2*)&Cf[(size_t)(row + 8) * ldc + col] = make_float2(c2, c3);
            } else if (OUT == 1) {
                *(__half2*)&Ch[(size_t)row * ldc + col] =
                    __halves2half2(__float2half_rn(c0), __float2half_rn(c1));
                *(__half2*)&Ch[(size_t)(row + 8) * ldc + col] =
                    __halves2half2(__float2half_rn(c2), __float2half_rn(c3));
            } else {
                // fused QKV: [0,512)=Q rope*log2e, [512,1024)=K rope, [1024,2048)=V^T
                if (col < 1024) {
                    const int d2 = (col & 63) >> 1;
                    const float2 r0 = rope[(size_t)(row & 2047) * 32 + d2];
                    const float2 r1 = rope[(size_t)((row + 8) & 2047) * 32 + d2];
                    const bool isq = (col < 512);
                    const float sc = isq ? LOG2E : 1.f;
                    f16* dst = isq ? Ch : Chk;
                    const int cc = col & 511;
                    *(__half2*)&dst[(size_t)row * HIDDEN + cc] =
                        __halves2half2(__float2half_rn(sc * (c0 * r0.x - c1 * r0.y)),
                                       __float2half_rn(sc * (c1 * r0.x + c0 * r0.y)));
                    *(__half2*)&dst[(size_t)(row + 8) * HIDDEN + cc] =
                        __halves2half2(__float2half_rn(sc * (c2 * r1.x - c3 * r1.y)),
                                       __float2half_rn(sc * (c3 * r1.x + c2 * r1.y)));
                } else {
                    const int n = col - 1024;
                    const size_t basev = (size_t)(row >> 11) * VDIM * SLEN;
                    const int s1 = row & 2047, s2 = (row + 8) & 2047;
                    Chv[basev + (size_t)n       * SLEN + s1] = __float2half_rn(c0);
                    Chv[basev + (size_t)(n + 1) * SLEN + s1] = __float2half_rn(c1);
                    Chv[basev + (size_t)n       * SLEN + s2] = __float2half_rn(c2);
                    Chv[basev + (size_t)(n + 1) * SLEN + s2] = __float2half_rn(c3);
                }
            }
        }
    }
}

// ---------------- flash attention: Q in regs, 3-stage KV, 1 sync/tile -------
__global__ __launch_bounds__(256, 1)
void flash_attn(const f16* __restrict__ Q, const f16* __restrict__ Kp,
                const f16* __restrict__ V, f16* __restrict__ Oh) {
    extern __shared__ char dsm[];
    unsigned s0 = (unsigned)__cvta_generic_to_shared(dsm);
    s0 = (s0 + 1023) & ~1023u;
    const int qt = blockIdx.x, z = blockIdx.y;
    const int b = z >> 3, h = z & 7;
    const int tid = threadIdx.x, lane = tid & 31, warp = tid >> 5;

    const f16* Qb = Q + ((size_t)(b * SLEN + qt * 128)) * HIDDEN + h * KD;
    const f16* Kb = Kp + (size_t)b * SLEN * HIDDEN + h * KD;
    const f16* Vb = V + ((size_t)b * VDIM + h * HSZ) * SLEN;

    const int rA = warp * 16 + (lane & 15);
    const int rB = (lane & 7) + ((lane >> 4) << 3);
    const int cBsel = (lane >> 3) & 1;

    // stage Q via smem into persistent regs
#pragma unroll
    for (int i = 0; i < 4; i++) {
        const int lin = i * 256 + tid;
        const int row = lin >> 3, c = lin & 7;
        cp16(s0 + row * 128 + ((c ^ (row & 7)) << 4), Qb + (size_t)row * HIDDEN + c * 8);
    }
    asm volatile("cp.async.commit_group;\ncp.async.wait_group 0;\n");
    __syncthreads();
    unsigned aq[4][4];
#pragma unroll
    for (int ks = 0; ks < 4; ks++) {
        const int lc = ks * 2 + (lane >> 4);
        ldsm4(aq[ks], s0 + rA * 128 + ((lc ^ (rA & 7)) << 4));
    }
    __syncthreads();

    auto issue_kv = [&](int kt) {
        const unsigned SK = s0 + (kt % 3) * 49152;
        const unsigned SV = SK + 16384;
#pragma unroll
        for (int i = 0; i < 12; i++) {
            const int lin = i * 256 + tid;
            if (lin < 1024) {
                const int row = lin >> 3, c = lin & 7;
                cp16(SK + row * 128 + ((c ^ (row & 7)) << 4),
                     Kb + (size_t)(kt * 128 + row) * HIDDEN + c * 8);
            } else {
                const int idx = lin - 1024;
                const int n = idx >> 4, c = idx & 15;
                cp16(SV + n * 256 + ((c ^ (n & 7)) << 4),
                     Vb + (size_t)n * SLEN + kt * 128 + c * 8);
            }
        }
        asm volatile("cp.async.commit_group;\n");
    };
    issue_kv(0);
    issue_kv(1);

    float O[16][4] = {};
    float m0 = -INFINITY, m1 = -INFINITY, l0 = 0.f, l1 = 0.f;

    for (int t = 0; t < 16; t++) {
        const unsigned SK = s0 + (t % 3) * 49152;
        const unsigned SV = SK + 16384;
        if (t + 1 < 16) {
            asm volatile("cp.async.wait_group 1;\n");
        } else {
            asm volatile("cp.async.wait_group 0;\n");
        }
        __syncthreads();
        if (t + 2 < 16) issue_kv(t + 2);

        // S = Q K^T (log2 domain: Q pre-scaled by log2e)
        float S[16][4] = {};
#pragma unroll
        for (int ks = 0; ks < 4; ks++) {
            const int lcB = ks * 2 + cBsel;
#pragma unroll
            for (int p = 0; p < 8; p++) {
                const int r2 = p * 16 + rB;
                unsigned tb[4];
                ldsm4(tb, SK + r2 * 128 + ((lcB ^ (r2 & 7)) << 4));
                mma16816(S[2*p],   aq[ks][0], aq[ks][1], aq[ks][2], aq[ks][3], tb[0], tb[1]);
                mma16816(S[2*p+1], aq[ks][0], aq[ks][1], aq[ks][2], aq[ks][3], tb[2], tb[3]);
            }
        }

        // online softmax (base-2)
        float mx0 = -INFINITY, mx1 = -INFINITY;
#pragma unroll
        for (int nt = 0; nt < 16; nt++) {
            mx0 = fmaxf(mx0, fmaxf(S[nt][0], S[nt][1]));
            mx1 = fmaxf(mx1, fmaxf(S[nt][2], S[nt][3]));
        }
        mx0 = fmaxf(mx0, __shfl_xor_sync(0xffffffffu, mx0, 1));
        mx0 = fmaxf(mx0, __shfl_xor_sync(0xffffffffu, mx0, 2));
        mx1 = fmaxf(mx1, __shfl_xor_sync(0xffffffffu, mx1, 1));
        mx1 = fmaxf(mx1, __shfl_xor_sync(0xffffffffu, mx1, 2));
        const float nm0 = fmaxf(m0, mx0), nm1 = fmaxf(m1, mx1);
        const float sc0 = exp2f(m0 - nm0), sc1 = exp2f(m1 - nm1);
        m0 = nm0; m1 = nm1;
        float rs0 = 0.f, rs1 = 0.f;
#pragma unroll
        for (int nt = 0; nt < 16; nt++) {
            S[nt][0] = exp2f(S[nt][0] - nm0);
            S[nt][1] = exp2f(S[nt][1] - nm0);
            S[nt][2] = exp2f(S[nt][2] - nm1);
            S[nt][3] = exp2f(S[nt][3] - nm1);
            rs0 += S[nt][0] + S[nt][1];
            rs1 += S[nt][2] + S[nt][3];
            O[nt][0] *= sc0; O[nt][1] *= sc0;
            O[nt][2] *= sc1; O[nt][3] *= sc1;
        }
        rs0 += __shfl_xor_sync(0xffffffffu, rs0, 1);
        rs0 += __shfl_xor_sync(0xffffffffu, rs0, 2);
        rs1 += __shfl_xor_sync(0xffffffffu, rs1, 1);
        rs1 += __shfl_xor_sync(0xffffffffu, rs1, 2);
        l0 = l0 * sc0 + rs0;
        l1 = l1 * sc1 + rs1;

        // O += P V
#pragma unroll
        for (int j = 0; j < 8; j++) {
            const unsigned a0 = h2pack(S[2*j][0],   S[2*j][1]);
            const unsigned a1 = h2pack(S[2*j][2],   S[2*j][3]);
            const unsigned a2 = h2pack(S[2*j+1][0], S[2*j+1][1]);
            const unsigned a3 = h2pack(S[2*j+1][2], S[2*j+1][3]);
            const int lcV = j * 2 + cBsel;
#pragma unroll
            for (int p = 0; p < 8; p++) {
                const int r2 = p * 16 + rB;
                unsigned tb[4];
                ldsm4(tb, SV + r2 * 256 + ((lcV ^ (r2 & 7)) << 4));
                mma16816(O[2*p],   a0, a1, a2, a3, tb[0], tb[1]);
                mma16816(O[2*p+1], a0, a1, a2, a3, tb[2], tb[3]);
            }
        }
    }

    const float inv0 = SCALING / l0, inv1 = SCALING / l1;
    const int g = lane >> 2, tg = lane & 3;
    const int srow = qt * 128 + warp * 16 + g;
    const size_t base0 = ((size_t)(b * SLEN) + srow) * VDIM + h * HSZ;
    const size_t base1 = base0 + (size_t)8 * VDIM;
#pragma unroll
    for (int nt = 0; nt < 16; nt++) {
        const int col = nt * 8 + tg * 2;
        *(__half2*)&Oh[base0 + col] =
            __halves2half2(__float2half_rn(O[nt][0] * inv0), __float2half_rn(O[nt][1] * inv0));
        *(__half2*)&Oh[base1 + col] =
            __halves2half2(__float2half_rn(O[nt][2] * inv1), __float2half_rn(O[nt][3] * inv1));
    }
}

// ---------------- batched weight transpose + fp16 ---------------------------
struct TSegs {
    const float* src[12];
    int dstoff[12];
    int K[12], N[12], tile0[12];
};

__global__ __launch_bounds__(256)
void transpose_cvt_all(TSegs segs, f16* __restrict__ dstbase) {
    __shared__ float t[32][33];
    const int tb = blockIdx.x;
    int s = 0;
#pragma unroll
    for (int i = 1; i < 12; i++) if (tb >= segs.tile0[i]) s = i;
    const int local = tb - segs.tile0[s];
    const int tilesX = segs.N[s] >> 5;
    const int nb = (local % tilesX) << 5;
    const int kb = (local / tilesX) << 5;
    const float* src = segs.src[s];
    f16* dst = dstbase + segs.dstoff[s];
    const int K = segs.K[s], N = segs.N[s];
    const int tx = threadIdx.x & 31, ty = threadIdx.x >> 5;
#pragma unroll
    for (int i = ty; i < 32; i += 8)
        t[i][tx] = src[(size_t)(kb + i) * N + nb + tx];
    __syncthreads();
#pragma unroll
    for (int i = ty; i < 32; i += 8)
        dst[(size_t)(nb + i) * K + kb + tx] = __float2half_rn(t[tx][i]);
}

// ---------------- rope table -------------------------------------------------
__global__ __launch_bounds__(256)
void build_rope(float2* __restrict__ rope) {
    const int idx = blockIdx.x * 256 + threadIdx.x;
    const int d2 = idx & 31, s = idx >> 5;
    const float base  = (2.f * d2 + 25.6f) / 89.6f;
    const float scale = powf(base, (float)(s - 1024) * (1.f / 512.f));
    const float invf  = powf(10000.f, -(float)d2 * (1.f / 32.f));
    float sv, cv;
    sincosf((float)s * invf, &sv, &cv);
    rope[idx] = make_float2(cv * scale, sv * scale);
}

// ---------------- elementwise fp32 -> fp16 ----------------------------------
__global__ __launch_bounds__(256)
void cvt_f16(const float* __restrict__ src, f16* __restrict__ dh) {
    const int i = blockIdx.x * 256 + threadIdx.x;
    dh[i] = __float2half_rn(src[i]);
}

// ---------------- block reduce / add_ln ------------------------------------
__device__ __forceinline__ float block_reduce(float v, float* sh, int op) {
#pragma unroll
    for (int o = 16; o; o >>= 1) {
        float t = __shfl_xor_sync(0xffffffffu, v, o);
        v = op ? fmaxf(v, t) : v + t;
    }
    if ((threadIdx.x & 31) == 0) sh[threadIdx.x >> 5] = v;
    __syncthreads();
    if (threadIdx.x < 32) {
        const int nw = blockDim.x >> 5;
        float t = (threadIdx.x < nw) ? sh[threadIdx.x] : (op ? -INFINITY : 0.f);
#pragma unroll
        for (int o = 16; o; o >>= 1) {
            float u = __shfl_xor_sync(0xffffffffu, t, o);
            t = op ? fmaxf(t, u) : t + u;
        }
        if (threadIdx.x == 0) sh[0] = t;
    }
    __syncthreads();
    float r = sh[0];
    __syncthreads();
    return r;
}

__global__ __launch_bounds__(256)
void add_ln(const float* __restrict__ a, const float* __restrict__ b,
            const float* __restrict__ g, const float* __restrict__ be,
            float* __restrict__ out, f16* __restrict__ oh) {
    __shared__ float sh[32];
    const size_t r = (size_t)blockIdx.x * HIDDEN;
    const int t = threadIdx.x;
    float v0 = a[r + t]       + b[r + t];
    float v1 = a[r + t + 256] + b[r + t + 256];
    float mean = block_reduce(v0 + v1, sh, 0) * (1.f / HIDDEN);
    float d0 = v0 - mean, d1 = v1 - mean;
    float var = block_reduce(d0 * d0 + d1 * d1, sh, 0) * (1.f / HIDDEN);
    float inv = rsqrtf(var + LN_EPS);
    const float o0 = d0 * inv * g[t]       + be[t];
    const float o1 = d1 * inv * g[t + 256] + be[t + 256];
    out[r + t]       = o0;
    out[r + t + 256] = o1;
    oh[r + t]       = __float2half_rn(o0);
    oh[r + t + 256] = __float2half_rn(o1);
}

// ---------------- driver ----------------------------------------------------
#define SMEM_MT4   (3*16384 + 1024)
#define SMEM_MT2   (3*12288 + 1024)
#define SMEM_FLASH (3*49152 + 1024)

extern "C" void kernel_launch(void* const* d_in, const int* in_sizes, int n_in,
                              void* d_out, int out_size) {
    const float* x   = (const float*)d_in[0];
    const float* Wq  = (const float*)d_in[1];
    const float* Wk  = (const float*)d_in[2];
    const float* Wv  = (const float*)d_in[3];
    const float* Wo  = (const float*)d_in[4];
    const float* W1  = (const float*)d_in[5];
    const float* b1  = (const float*)d_in[6];
    const float* W2  = (const float*)d_in[7];
    const float* b2  = (const float*)d_in[8];
    const float* g1  = (const float*)d_in[9];
    const float* be1 = (const float*)d_in[10];
    const float* g2  = (const float*)d_in[11];
    const float* be2 = (const float*)d_in[12];

    float *proj, *y, *xb;
    f16 *xh, *qh, *kh, *vt, *att, *yh, *f1h, *wt;
    float2* rope;
    cudaGetSymbolAddress((void**)&proj, g_proj);
    cudaGetSymbolAddress((void**)&y,    g_y);
    cudaGetSymbolAddress((void**)&xb,   g_x);
    cudaGetSymbolAddress((void**)&xh,   g_xh);
    cudaGetSymbolAddress((void**)&qh,   g_qh);
    cudaGetSymbolAddress((void**)&kh,   g_kh);
    cudaGetSymbolAddress((void**)&vt,   g_vt);
    cudaGetSymbolAddress((void**)&att,  g_att);
    cudaGetSymbolAddress((void**)&yh,   g_yh);
    cudaGetSymbolAddress((void**)&f1h,  g_f1h);
    cudaGetSymbolAddress((void**)&wt,   g_wt);
    cudaGetSymbolAddress((void**)&rope, g_rope);

    static bool attr_done = false;
    if (!attr_done) {
        cudaFuncSetAttribute((const void*)gemm_f16<4,false,false,4>, cudaFuncAttributeMaxDynamicSharedMemorySize, SMEM_MT4);
        cudaFuncSetAttribute((const void*)gemm_f16<4,true,true,1>,   cudaFuncAttributeMaxDynamicSharedMemorySize, SMEM_MT4);
        cudaFuncSetAttribute((const void*)gemm_f16<2,false,false,0>, cudaFuncAttributeMaxDynamicSharedMemorySize, SMEM_MT2);
        cudaFuncSetAttribute((const void*)gemm_f16<2,true,false,0>,  cudaFuncAttributeMaxDynamicSharedMemorySize, SMEM_MT2);
        cudaFuncSetAttribute((const void*)flash_attn,                cudaFuncAttributeMaxDynamicSharedMemorySize, SMEM_FLASH);
        attr_done = true;
    }

    const dim3 T(256);

    // ---- one batched transpose launch for all 12 weight matrices ----
    {
        TSegs segs;
        int tile = 0;
        int si = 0;
        for (int l = 0; l < 2; l++) {
            const float* srcs[6] = {Wq + (size_t)l*HIDDEN*HIDDEN, Wk + (size_t)l*HIDDEN*HIDDEN,
                                    Wv + (size_t)l*HIDDEN*VDIM,   Wo + (size_t)l*VDIM*HIDDEN,
                                    W1 + (size_t)l*HIDDEN*FFNDIM, W2 + (size_t)l*FFNDIM*HIDDEN};
            const int offs[6] = {OFF_WQ, OFF_WK, OFF_WV, OFF_WO, OFF_W1, OFF_W2};
            const int Ks[6]   = {HIDDEN, HIDDEN, HIDDEN, VDIM, HIDDEN, FFNDIM};
            const int Ns[6]   = {HIDDEN, HIDDEN, VDIM, HIDDEN, FFNDIM, HIDDEN};
            for (int j = 0; j < 6; j++, si++) {
                segs.src[si] = srcs[j];
                segs.dstoff[si] = l * WT_PER_LAYER + offs[j];
                segs.K[si] = Ks[j]; segs.N[si] = Ns[j];
                segs.tile0[si] = tile;
                tile += (Ks[j] >> 5) * (Ns[j] >> 5);
            }
        }
        transpose_cvt_all<<<tile, T>>>(segs, wt);
    }

    build_rope<<<(SLEN*32)/256, T>>>(rope);
    cvt_f16<<<(ROWS*HIDDEN)/256, T>>>(x, xh);

    for (int i = 0; i < 2; i++) {
        const float* xin  = i ? xb : x;
        float*       xout = i ? (float*)d_out : xb;
        f16* base = wt + (size_t)i * WT_PER_LAYER;

        // fused QKV projection: N=2048 = [Q|K|V], tile 128x128
        gemm_f16<4,false,false,4><<<dim3(16, ROWS/128), T, SMEM_MT4>>>(
            xh, base+OFF_WQ, nullptr, rope, nullptr, qh, kh, vt,
            HIDDEN, HIDDEN, HIDDEN, 0);

        flash_attn<<<dim3(SLEN/128, BSZ*HEADS), T, SMEM_FLASH>>>(qh, kh, vt, att);

        // output projection (tile 64x128)
        gemm_f16<2,false,false,0><<<dim3(4, ROWS/64), T, SMEM_MT2>>>(
            att, base+OFF_WO, nullptr, nullptr, proj, nullptr, nullptr, nullptr,
            VDIM, VDIM, VDIM, HIDDEN);

        add_ln<<<ROWS, T>>>(xin, proj, g1 + i*HIDDEN, be1 + i*HIDDEN, y, yh);

        // FFN1 (tile 128x128) / FFN2 (tile 64x128)
        gemm_f16<4,true,true,1><<<dim3(16, ROWS/128), T, SMEM_MT4>>>(
            yh, base+OFF_W1, b1 + i*FFNDIM, nullptr, nullptr, f1h, nullptr, nullptr,
            HIDDEN, HIDDEN, HIDDEN, FFNDIM);
        gemm_f16<2,true,false,0><<<dim3(4, ROWS/64), T, SMEM_MT2>>>(
            f1h, base+OFF_W2, b2 + i*HIDDEN, nullptr, proj, nullptr, nullptr, nullptr,
            FFNDIM, FFNDIM, FFNDIM, HIDDEN);

        add_ln<<<ROWS, T>>>(y, proj, g2 + i*HIDDEN, be2 + i*HIDDEN, xout, xh);
    }
}